// round 4
// baseline (speedup 1.0000x reference)
#include <cuda_runtime.h>
#include <cuda_bf16.h>

#define N_BATCH 4096
#define T_SEQ   200

// ---------------- device scratch (no allocs allowed) ----------------
// wt1[k*512 + t*2 + jj] = W1[(t + 256*jj)*128 + k]   (k<128, t<256, jj<2)
__device__ float g_wt1[128 * 512];
// wt2[k*256 + j] = W2[j*512 + k]                     (k<512, j<256)
__device__ float g_wt2[512 * 256];
// wt3[k*128 + j] = W3[j*256 + k]                     (k<256, j<128)
__device__ float g_wt3[256 * 128];

// ---------------- f32x2 helpers (sm_103a packed fp32) ----------------
typedef unsigned long long u64;

__device__ __forceinline__ u64 pk2(float lo, float hi) {
    u64 r; asm("mov.b64 %0, {%1,%2};" : "=l"(r) : "f"(lo), "f"(hi)); return r;
}
__device__ __forceinline__ float2 upk(u64 v) {
    float2 f; asm("mov.b64 {%0,%1}, %2;" : "=f"(f.x), "=f"(f.y) : "l"(v)); return f;
}
__device__ __forceinline__ void fma2(u64& d, u64 a, u64 b) {
    asm("fma.rn.f32x2 %0, %1, %2, %0;" : "+l"(d) : "l"(a), "l"(b));
}

// ---------------- 1) weight transpose (coalesced reads) ----------------
__global__ void transpose_kernel(const float* __restrict__ W1,
                                 const float* __restrict__ W2,
                                 const float* __restrict__ W3) {
    int idx = blockIdx.x * blockDim.x + threadIdx.x;
    if (idx < 65536) {                       // W1: 512x128
        int j = idx >> 7, k = idx & 127;
        int t = j & 255, jj = j >> 8;
        g_wt1[k * 512 + t * 2 + jj] = W1[idx];
    } else if (idx < 65536 + 131072) {       // W2: 256x512
        int i2 = idx - 65536;
        int j = i2 >> 9, k = i2 & 511;
        g_wt2[k * 256 + j] = W2[i2];
    } else if (idx < 65536 + 131072 + 32768) { // W3: 128x256
        int i3 = idx - 65536 - 131072;
        int j = i3 >> 8, k = i3 & 255;
        g_wt3[k * 128 + j] = W3[i3];
    }
}

// ---------------- 2) fused pool + MLP: 16 rows per block, 256 threads ----------------
// Activation layout: [k][pair], padded to 10 u64 per k (16B-aligned LDS.128 pair loads).
// u64 word = (row 2p value, row 2p+1 value).
// Shared pool S (71.7 KB):
//   A1  = S + 0     : 512 k * 10  (layer1 out)
//   B2  = S + 5120  : 256 k * 10  (layer2 out)
//   BIN = S + 7680  : 128 k * 10  (pooled in; reused as layer3 out A3)
#define PADK 10

__global__ void __launch_bounds__(256, 2) mlp_kernel(
        const int*   __restrict__ x,
        const int*   __restrict__ lengths,
        const float* __restrict__ emb,
        const float* __restrict__ b1,
        const float* __restrict__ b2,
        const float* __restrict__ b3,
        const float* __restrict__ W4,
        const float* __restrict__ b4,
        float* __restrict__ out) {
    __shared__ __align__(16) u64 S[512 * PADK + 256 * PADK + 128 * PADK];
    u64* A1  = S;
    u64* B2  = S + 512 * PADK;
    u64* BIN = S + 512 * PADK + 256 * PADK;
    u64* A3  = BIN;

    int tid  = threadIdx.x;
    int w    = tid >> 5;          // warp 0..7 == pair p
    int lane = tid & 31;
    int r0   = blockIdx.x * 16;

    // ---- pooling: warp w pools rows r0+2w (lo), r0+2w+1 (hi) ----
    {
        const float4* emb4 = (const float4*)emb;
        float4 accs[2];
        #pragma unroll
        for (int s = 0; s < 2; ++s) {
            int row = r0 + 2 * w + s;
            const int* xr = x + row * T_SEQ;
            int len = lengths[row];
            float4 acc = make_float4(0.f, 0.f, 0.f, 0.f);
            int t = 0;
            for (; t + 8 <= len; t += 8) {
                int4 ia = *(const int4*)(xr + t);
                int4 ib = *(const int4*)(xr + t + 4);
                float4 v0 = emb4[ia.x * 32 + lane];
                float4 v1 = emb4[ia.y * 32 + lane];
                float4 v2 = emb4[ia.z * 32 + lane];
                float4 v3 = emb4[ia.w * 32 + lane];
                float4 v4 = emb4[ib.x * 32 + lane];
                float4 v5 = emb4[ib.y * 32 + lane];
                float4 v6 = emb4[ib.z * 32 + lane];
                float4 v7 = emb4[ib.w * 32 + lane];
                acc.x += ((v0.x + v1.x) + (v2.x + v3.x)) + ((v4.x + v5.x) + (v6.x + v7.x));
                acc.y += ((v0.y + v1.y) + (v2.y + v3.y)) + ((v4.y + v5.y) + (v6.y + v7.y));
                acc.z += ((v0.z + v1.z) + (v2.z + v3.z)) + ((v4.z + v5.z) + (v6.z + v7.z));
                acc.w += ((v0.w + v1.w) + (v2.w + v3.w)) + ((v4.w + v5.w) + (v6.w + v7.w));
            }
            for (; t < len; ++t) {
                float4 a = emb4[xr[t] * 32 + lane];
                acc.x += a.x; acc.y += a.y; acc.z += a.z; acc.w += a.w;
            }
            float inv = 1.0f / (float)len;
            acc.x *= inv; acc.y *= inv; acc.z *= inv; acc.w *= inv;
            accs[s] = acc;
        }
        // BIN[k*PADK + w], lane owns k = 4*lane .. 4*lane+3
        BIN[(4 * lane + 0) * PADK + w] = pk2(accs[0].x, accs[1].x);
        BIN[(4 * lane + 1) * PADK + w] = pk2(accs[0].y, accs[1].y);
        BIN[(4 * lane + 2) * PADK + w] = pk2(accs[0].z, accs[1].z);
        BIN[(4 * lane + 3) * PADK + w] = pk2(accs[0].w, accs[1].w);
    }
    __syncthreads();

    // ---- layer 1: 128 -> 512; outputs j = tid + 256*jj, jj<2 ----
    {
        u64 acc[8][2];
        #pragma unroll
        for (int p = 0; p < 8; ++p) { acc[p][0] = 0ULL; acc[p][1] = 0ULL; }

        const float2* Wt = (const float2*)g_wt1;   // [k][t] -> (jj0, jj1)
        #pragma unroll 8
        for (int k = 0; k < 128; ++k) {
            float2 wv = Wt[k * 256 + tid];
            u64 w0 = pk2(wv.x, wv.x), w1 = pk2(wv.y, wv.y);
            ulonglong2 a01 = *(const ulonglong2*)(BIN + k * PADK + 0);
            ulonglong2 a23 = *(const ulonglong2*)(BIN + k * PADK + 2);
            ulonglong2 a45 = *(const ulonglong2*)(BIN + k * PADK + 4);
            ulonglong2 a67 = *(const ulonglong2*)(BIN + k * PADK + 6);
            fma2(acc[0][0], a01.x, w0); fma2(acc[0][1], a01.x, w1);
            fma2(acc[1][0], a01.y, w0); fma2(acc[1][1], a01.y, w1);
            fma2(acc[2][0], a23.x, w0); fma2(acc[2][1], a23.x, w1);
            fma2(acc[3][0], a23.y, w0); fma2(acc[3][1], a23.y, w1);
            fma2(acc[4][0], a45.x, w0); fma2(acc[4][1], a45.x, w1);
            fma2(acc[5][0], a45.y, w0); fma2(acc[5][1], a45.y, w1);
            fma2(acc[6][0], a67.x, w0); fma2(acc[6][1], a67.x, w1);
            fma2(acc[7][0], a67.y, w0); fma2(acc[7][1], a67.y, w1);
        }
        #pragma unroll
        for (int jj = 0; jj < 2; ++jj) {
            float bj = b1[tid + 256 * jj];
            int n1 = tid + 256 * jj;
            #pragma unroll
            for (int p = 0; p < 8; ++p) {
                float2 v = upk(acc[p][jj]);
                v.x = fmaxf(v.x + bj, 0.f);
                v.y = fmaxf(v.y + bj, 0.f);
                A1[n1 * PADK + p] = pk2(v.x, v.y);
            }
        }
    }
    __syncthreads();

    // ---- layer 2: 512 -> 256; output j = tid ----
    {
        u64 acc[8];
        #pragma unroll
        for (int p = 0; p < 8; ++p) acc[p] = 0ULL;

        #pragma unroll 8
        for (int k = 0; k < 512; ++k) {
            float wv = g_wt2[k * 256 + tid];       // coalesced
            u64 ws = pk2(wv, wv);
            ulonglong2 a01 = *(const ulonglong2*)(A1 + k * PADK + 0);
            ulonglong2 a23 = *(const ulonglong2*)(A1 + k * PADK + 2);
            ulonglong2 a45 = *(const ulonglong2*)(A1 + k * PADK + 4);
            ulonglong2 a67 = *(const ulonglong2*)(A1 + k * PADK + 6);
            fma2(acc[0], a01.x, ws); fma2(acc[1], a01.y, ws);
            fma2(acc[2], a23.x, ws); fma2(acc[3], a23.y, ws);
            fma2(acc[4], a45.x, ws); fma2(acc[5], a45.y, ws);
            fma2(acc[6], a67.x, ws); fma2(acc[7], a67.y, ws);
        }
        float bj = b2[tid];
        #pragma unroll
        for (int p = 0; p < 8; ++p) {
            float2 v = upk(acc[p]);
            v.x = fmaxf(v.x + bj, 0.f);
            v.y = fmaxf(v.y + bj, 0.f);
            B2[tid * PADK + p] = pk2(v.x, v.y);
        }
    }
    __syncthreads();

    // ---- layer 3: 256 -> 128; j = tid&127, pair-range split by tid>>7 ----
    {
        int j     = tid & 127;
        int pbase = (tid >> 7) * 4;                // 0 or 4
        u64 acc[4];
        #pragma unroll
        for (int q = 0; q < 4; ++q) acc[q] = 0ULL;

        #pragma unroll 8
        for (int k = 0; k < 256; ++k) {
            float wv = g_wt3[k * 128 + j];         // coalesced
            u64 ws = pk2(wv, wv);
            ulonglong2 a01 = *(const ulonglong2*)(B2 + k * PADK + pbase + 0);
            ulonglong2 a23 = *(const ulonglong2*)(B2 + k * PADK + pbase + 2);
            fma2(acc[0], a01.x, ws); fma2(acc[1], a01.y, ws);
            fma2(acc[2], a23.x, ws); fma2(acc[3], a23.y, ws);
        }
        float bj = b3[j];
        #pragma unroll
        for (int q = 0; q < 4; ++q) {
            float2 v = upk(acc[q]);
            v.x = fmaxf(v.x + bj, 0.f);
            v.y = fmaxf(v.y + bj, 0.f);
            A3[j * PADK + pbase + q] = pk2(v.x, v.y);
        }
    }
    __syncthreads();

    // ---- layer 4: 128 -> 2 (one warp: r = tid>>1, jo = tid&1) ----
    if (tid < 32) {
        int r  = tid >> 1;             // 0..15
        int jo = tid & 1;
        int p = r >> 1, h = r & 1;
        float acc = b4[jo];
        #pragma unroll 8
        for (int k = 0; k < 128; ++k) {
            float2 v = upk(A3[k * PADK + p]);
            acc += (h ? v.y : v.x) * W4[jo * 128 + k];
        }
        out[(r0 + r) * 2 + jo] = acc;
    }
}

// ---------------- launch ----------------
extern "C" void kernel_launch(void* const* d_in, const int* in_sizes, int n_in,
                              void* d_out, int out_size) {
    const int*   x       = (const int*)  d_in[0];
    const int*   lengths = (const int*)  d_in[1];
    const float* emb     = (const float*)d_in[2];
    const float* W1      = (const float*)d_in[3];
    const float* b1      = (const float*)d_in[4];
    const float* W2      = (const float*)d_in[5];
    const float* b2      = (const float*)d_in[6];
    const float* W3      = (const float*)d_in[7];
    const float* b3      = (const float*)d_in[8];
    const float* W4      = (const float*)d_in[9];
    const float* b4      = (const float*)d_in[10];
    float* out = (float*)d_out;

    transpose_kernel<<<(229376 + 255) / 256, 256>>>(W1, W2, W3);
    mlp_kernel<<<N_BATCH / 16, 256>>>(x, lengths, emb, b1, b2, b3, W4, b4, out);
}

// round 5
// speedup vs baseline: 1.7182x; 1.7182x over previous
#include <cuda_runtime.h>
#include <cuda_bf16.h>

#define N_BATCH 4096
#define T_SEQ   200

// ---------------- device scratch (no allocs allowed) ----------------
// wt1[k*512 + t*2 + jj] = W1[(t + 256*jj)*128 + k]   (k<128, t<256, jj<2)
__device__ float g_wt1[128 * 512];
// wt2[k*256 + j] = W2[j*512 + k]                     (k<512, j<256)
__device__ float g_wt2[512 * 256];
// wt3[k*128 + j] = W3[j*256 + k]                     (k<256, j<128)
__device__ float g_wt3[256 * 128];

// ---------------- f32x2 helpers (sm_103a packed fp32) ----------------
typedef unsigned long long u64;

__device__ __forceinline__ u64 pk2(float lo, float hi) {
    u64 r; asm("mov.b64 %0, {%1,%2};" : "=l"(r) : "f"(lo), "f"(hi)); return r;
}
__device__ __forceinline__ float2 upk(u64 v) {
    float2 f; asm("mov.b64 {%0,%1}, %2;" : "=f"(f.x), "=f"(f.y) : "l"(v)); return f;
}
__device__ __forceinline__ void fma2(u64& d, u64 a, u64 b) {
    asm("fma.rn.f32x2 %0, %1, %2, %0;" : "+l"(d) : "l"(a), "l"(b));
}

// ---------------- 1) weight transpose (coalesced reads) ----------------
__global__ void transpose_kernel(const float* __restrict__ W1,
                                 const float* __restrict__ W2,
                                 const float* __restrict__ W3) {
    int idx = blockIdx.x * blockDim.x + threadIdx.x;
    if (idx < 65536) {                       // W1: 512x128
        int j = idx >> 7, k = idx & 127;
        int t = j & 255, jj = j >> 8;
        g_wt1[k * 512 + t * 2 + jj] = W1[idx];
    } else if (idx < 65536 + 131072) {       // W2: 256x512
        int i2 = idx - 65536;
        int j = i2 >> 9, k = i2 & 511;
        g_wt2[k * 256 + j] = W2[i2];
    } else if (idx < 65536 + 131072 + 32768) { // W3: 128x256
        int i3 = idx - 65536 - 131072;
        int j = i3 >> 8, k = i3 & 255;
        g_wt3[k * 128 + j] = W3[i3];
    }
}

// ---------------- 2) fused pool + MLP: 16 rows per block, 512 threads ----------------
// Activation u64 word = (row 2p value, row 2p+1 value), layout [pair][k].
// Smem union (exactly 48 KB):
//   A1 = S          : 8 pairs * 512  (layer1 out; region reused as A3 layer3 out)
//   B2 = S + 4096   : 8 pairs * 256  (layer2 out; first 1024 words reused as BIN pooled-in)
__global__ void __launch_bounds__(512) mlp_kernel(
        const int*   __restrict__ x,
        const int*   __restrict__ lengths,
        const float* __restrict__ emb,
        const float* __restrict__ b1,
        const float* __restrict__ b2,
        const float* __restrict__ b3,
        const float* __restrict__ W4,
        const float* __restrict__ b4,
        float* __restrict__ out) {
    __shared__ __align__(16) u64 S[8 * 512 + 8 * 256];   // 48 KB
    u64* A1  = S;                 // [p*512 + n1]
    u64* B2  = S + 8 * 512;       // [p*256 + j]
    u64* BIN = B2;                // [p*128 + k] (dead after layer 1)
    u64* A3  = A1;                // [p*128 + j] (written in layer 3)

    int tid  = threadIdx.x;
    int w    = tid >> 5;          // warp 0..15 == row within block
    int lane = tid & 31;
    int r0   = blockIdx.x * 16;

    // ---- pooling: warp w pools row r0+w ----
    {
        int row = r0 + w;
        const int* xr = x + row * T_SEQ;
        int len = lengths[row];
        const float4* emb4 = (const float4*)emb;
        float4 acc = make_float4(0.f, 0.f, 0.f, 0.f);
        int t = 0;
        for (; t + 8 <= len; t += 8) {
            int4 ia = *(const int4*)(xr + t);
            int4 ib = *(const int4*)(xr + t + 4);
            float4 v0 = emb4[ia.x * 32 + lane];
            float4 v1 = emb4[ia.y * 32 + lane];
            float4 v2 = emb4[ia.z * 32 + lane];
            float4 v3 = emb4[ia.w * 32 + lane];
            float4 v4 = emb4[ib.x * 32 + lane];
            float4 v5 = emb4[ib.y * 32 + lane];
            float4 v6 = emb4[ib.z * 32 + lane];
            float4 v7 = emb4[ib.w * 32 + lane];
            acc.x += ((v0.x + v1.x) + (v2.x + v3.x)) + ((v4.x + v5.x) + (v6.x + v7.x));
            acc.y += ((v0.y + v1.y) + (v2.y + v3.y)) + ((v4.y + v5.y) + (v6.y + v7.y));
            acc.z += ((v0.z + v1.z) + (v2.z + v3.z)) + ((v4.z + v5.z) + (v6.z + v7.z));
            acc.w += ((v0.w + v1.w) + (v2.w + v3.w)) + ((v4.w + v5.w) + (v6.w + v7.w));
        }
        for (; t < len; ++t) {
            float4 a = emb4[xr[t] * 32 + lane];
            acc.x += a.x; acc.y += a.y; acc.z += a.z; acc.w += a.w;
        }
        float inv = 1.0f / (float)len;
        acc.x *= inv; acc.y *= inv; acc.z *= inv; acc.w *= inv;

        // write float halves of the pair words: p = w>>1, s = w&1 (lo/hi)
        float* Bf = (float*)BIN;
        int p = w >> 1, s = w & 1;
        Bf[(p * 128 + 4 * lane + 0) * 2 + s] = acc.x;
        Bf[(p * 128 + 4 * lane + 1) * 2 + s] = acc.y;
        Bf[(p * 128 + 4 * lane + 2) * 2 + s] = acc.z;
        Bf[(p * 128 + 4 * lane + 3) * 2 + s] = acc.w;
    }
    __syncthreads();

    // ---- layer 1: 128 -> 512; j = (tid&255) + 256*jj (jj<2), pairs pbase..pbase+3 ----
    {
        int jhalf = tid & 255;
        int pbase = (tid >> 8) * 4;            // 0 or 4
        u64 acc[4][2];
        #pragma unroll
        for (int q = 0; q < 4; ++q) { acc[q][0] = 0ULL; acc[q][1] = 0ULL; }

        const float2* Wt = (const float2*)g_wt1;   // [k][t] -> (jj0, jj1)
        #pragma unroll 4
        for (int k = 0; k < 128; ++k) {
            float2 wv = Wt[k * 256 + jhalf];
            u64 w0 = pk2(wv.x, wv.x), w1 = pk2(wv.y, wv.y);
            #pragma unroll
            for (int q = 0; q < 4; ++q) {
                u64 a = BIN[(pbase + q) * 128 + k];   // warp-uniform broadcast
                fma2(acc[q][0], a, w0);
                fma2(acc[q][1], a, w1);
            }
        }
        // NOTE: BIN becomes dead only after ALL threads finish layer 1 reads.
        __syncthreads();
        #pragma unroll
        for (int jj = 0; jj < 2; ++jj) {
            float bj = b1[jhalf + 256 * jj];
            int n1 = jhalf + 256 * jj;
            #pragma unroll
            for (int q = 0; q < 4; ++q) {
                float2 v = upk(acc[q][jj]);
                v.x = fmaxf(v.x + bj, 0.f);
                v.y = fmaxf(v.y + bj, 0.f);
                A1[(pbase + q) * 512 + n1] = pk2(v.x, v.y);
            }
        }
    }
    __syncthreads();

    // ---- layer 2: 512 -> 256; j = tid&255, pairs pbase..pbase+3 ----
    // (B2 overlaps BIN, which is dead now.)
    {
        int j     = tid & 255;
        int pbase = (tid >> 8) * 4;
        u64 acc[4];
        #pragma unroll
        for (int q = 0; q < 4; ++q) acc[q] = 0ULL;

        #pragma unroll 4
        for (int k = 0; k < 512; ++k) {
            float wv = g_wt2[k * 256 + j];          // coalesced (dup across halves -> L1 hit)
            u64 ws = pk2(wv, wv);
            #pragma unroll
            for (int q = 0; q < 4; ++q) {
                u64 a = A1[(pbase + q) * 512 + k];  // warp-uniform broadcast
                fma2(acc[q], a, ws);
            }
        }
        __syncthreads();                            // A1 reads done before B2 write? no: B2 != A1. Order: write B2 now.
        float bj = b2[j];
        #pragma unroll
        for (int q = 0; q < 4; ++q) {
            float2 v = upk(acc[q]);
            v.x = fmaxf(v.x + bj, 0.f);
            v.y = fmaxf(v.y + bj, 0.f);
            B2[(pbase + q) * 256 + j] = pk2(v.x, v.y);
        }
    }
    __syncthreads();

    // ---- layer 3: 256 -> 128; j = tid&127, pairs pbase..pbase+1 ----
    // (A3 overlaps A1; all A1 reads completed at the sync above.)
    {
        int j     = tid & 127;
        int pbase = (tid >> 7) * 2;                 // 0,2,4,6
        u64 acc[2];
        acc[0] = 0ULL; acc[1] = 0ULL;

        #pragma unroll 8
        for (int k = 0; k < 256; ++k) {
            float wv = g_wt3[k * 128 + j];          // coalesced (dup across quarters)
            u64 ws = pk2(wv, wv);
            fma2(acc[0], B2[(pbase + 0) * 256 + k], ws);
            fma2(acc[1], B2[(pbase + 1) * 256 + k], ws);
        }
        float bj = b3[j];
        #pragma unroll
        for (int q = 0; q < 2; ++q) {
            float2 v = upk(acc[q]);
            v.x = fmaxf(v.x + bj, 0.f);
            v.y = fmaxf(v.y + bj, 0.f);
            A3[(pbase + q) * 128 + j] = pk2(v.x, v.y);
        }
    }
    __syncthreads();

    // ---- layer 4: 128 -> 2 (one warp: r = tid>>1, jo = tid&1) ----
    if (tid < 32) {
        int r  = tid >> 1;             // 0..15
        int jo = tid & 1;
        int p = r >> 1, h = r & 1;
        float acc = b4[jo];
        #pragma unroll 8
        for (int k = 0; k < 128; ++k) {
            float2 v = upk(A3[p * 128 + k]);
            acc += (h ? v.y : v.x) * W4[jo * 128 + k];
        }
        out[(r0 + r) * 2 + jo] = acc;
    }
}

// ---------------- launch ----------------
extern "C" void kernel_launch(void* const* d_in, const int* in_sizes, int n_in,
                              void* d_out, int out_size) {
    const int*   x       = (const int*)  d_in[0];
    const int*   lengths = (const int*)  d_in[1];
    const float* emb     = (const float*)d_in[2];
    const float* W1      = (const float*)d_in[3];
    const float* b1      = (const float*)d_in[4];
    const float* W2      = (const float*)d_in[5];
    const float* b2      = (const float*)d_in[6];
    const float* W3      = (const float*)d_in[7];
    const float* b3      = (const float*)d_in[8];
    const float* W4      = (const float*)d_in[9];
    const float* b4      = (const float*)d_in[10];
    float* out = (float*)d_out;

    transpose_kernel<<<(229376 + 255) / 256, 256>>>(W1, W2, W3);
    mlp_kernel<<<N_BATCH / 16, 512>>>(x, lengths, emb, b1, b2, b3, W4, b4, out);
}

// round 6
// speedup vs baseline: 1.8251x; 1.0623x over previous
#include <cuda_runtime.h>
#include <cuda_bf16.h>

#define N_BATCH 4096
#define T_SEQ   200
#define PADK    10

// ---------------- device scratch (no allocs allowed) ----------------
// wt1[k*512 + jg*4 + jj] = W1[(jg + 128*jj)*128 + k]   (k<128, jg<128, jj<4)
__device__ float g_wt1[128 * 512];
// wt2[k*256 + jg*2 + jj] = W2[(jg + 128*jj)*512 + k]   (k<512, jg<128, jj<2)
__device__ float g_wt2[512 * 256];
// wt3[k*128 + j]         = W3[j*256 + k]               (k<256, j<128)
__device__ float g_wt3[256 * 128];

// ---------------- f32x2 helpers (sm_103a packed fp32) ----------------
typedef unsigned long long u64;

__device__ __forceinline__ u64 pk2(float lo, float hi) {
    u64 r; asm("mov.b64 %0, {%1,%2};" : "=l"(r) : "f"(lo), "f"(hi)); return r;
}
__device__ __forceinline__ float2 upk(u64 v) {
    float2 f; asm("mov.b64 {%0,%1}, %2;" : "=f"(f.x), "=f"(f.y) : "l"(v)); return f;
}
__device__ __forceinline__ void fma2(u64& d, u64 a, u64 b) {
    asm("fma.rn.f32x2 %0, %1, %2, %0;" : "+l"(d) : "l"(a), "l"(b));
}

// ---------------- 1) weight transpose (coalesced reads) ----------------
__global__ void transpose_kernel(const float* __restrict__ W1,
                                 const float* __restrict__ W2,
                                 const float* __restrict__ W3) {
    int idx = blockIdx.x * blockDim.x + threadIdx.x;
    if (idx < 65536) {                         // W1: 512x128 (j*128+k)
        int j = idx >> 7, k = idx & 127;
        int jg = j & 127, jj = j >> 7;
        g_wt1[k * 512 + jg * 4 + jj] = W1[idx];
    } else if (idx < 65536 + 131072) {         // W2: 256x512 (j*512+k)
        int i2 = idx - 65536;
        int j = i2 >> 9, k = i2 & 511;
        int jg = j & 127, jj = j >> 7;
        g_wt2[k * 256 + jg * 2 + jj] = W2[i2];
    } else if (idx < 65536 + 131072 + 32768) { // W3: 128x256 (j*256+k)
        int i3 = idx - 65536 - 131072;
        int j = i3 >> 8, k = i3 & 255;
        g_wt3[k * 128 + j] = W3[i3];
    }
}

// ---------------- 2) fused pool + MLP: 16 rows per block, 512 threads ----------------
// Activation u64 word = (row 2p value, row 2p+1 value), layout [k][pair] padded to
// PADK=10 u64 per k (16B-aligned pair loads, conflict-free stores).
// Smem:
//   A1  = S        : 512*10 u64 (40KB)  layer1 out; first 1280 reused as A3 (layer3 out)
//   B2  = S+5120   : 256*10 u64 (20KB)  layer2 out; first 1280 reused as BIN (pooled in)
__global__ void __launch_bounds__(512, 2) mlp_kernel(
        const int*   __restrict__ x,
        const int*   __restrict__ lengths,
        const float* __restrict__ emb,
        const float* __restrict__ b1,
        const float* __restrict__ b2,
        const float* __restrict__ b3,
        const float* __restrict__ W4,
        const float* __restrict__ b4,
        float* __restrict__ out) {
    __shared__ __align__(16) u64 S[512 * PADK + 256 * PADK];   // 60 KB
    u64* A1  = S;                      // [k*PADK + p], k<512
    u64* B2  = S + 512 * PADK;         // [k*PADK + p], k<256
    u64* BIN = B2;                     // [k*PADK + p], k<128 (dead after layer 1)
    u64* A3  = A1;                     // [j*PADK + p], j<128 (written in layer 3)

    int tid   = threadIdx.x;
    int w     = tid >> 5;              // warp 0..15 == row within block
    int lane  = tid & 31;
    int jg    = tid & 127;             // output-group index
    int pbase = (tid >> 7) * 2;        // pair base: 0,2,4,6 (uniform per warp)
    int r0    = blockIdx.x * 16;

    // ---- pooling: warp w pools row r0+w ----
    {
        int row = r0 + w;
        const int* xr = x + row * T_SEQ;
        int len = lengths[row];
        const float4* emb4 = (const float4*)emb;
        float4 acc = make_float4(0.f, 0.f, 0.f, 0.f);
        int t = 0;
        for (; t + 8 <= len; t += 8) {
            int4 ia = *(const int4*)(xr + t);
            int4 ib = *(const int4*)(xr + t + 4);
            float4 v0 = emb4[ia.x * 32 + lane];
            float4 v1 = emb4[ia.y * 32 + lane];
            float4 v2 = emb4[ia.z * 32 + lane];
            float4 v3 = emb4[ia.w * 32 + lane];
            float4 v4 = emb4[ib.x * 32 + lane];
            float4 v5 = emb4[ib.y * 32 + lane];
            float4 v6 = emb4[ib.z * 32 + lane];
            float4 v7 = emb4[ib.w * 32 + lane];
            acc.x += ((v0.x + v1.x) + (v2.x + v3.x)) + ((v4.x + v5.x) + (v6.x + v7.x));
            acc.y += ((v0.y + v1.y) + (v2.y + v3.y)) + ((v4.y + v5.y) + (v6.y + v7.y));
            acc.z += ((v0.z + v1.z) + (v2.z + v3.z)) + ((v4.z + v5.z) + (v6.z + v7.z));
            acc.w += ((v0.w + v1.w) + (v2.w + v3.w)) + ((v4.w + v5.w) + (v6.w + v7.w));
        }
        for (; t < len; ++t) {
            float4 a = emb4[xr[t] * 32 + lane];
            acc.x += a.x; acc.y += a.y; acc.z += a.z; acc.w += a.w;
        }
        float inv = 1.0f / (float)len;
        acc.x *= inv; acc.y *= inv; acc.z *= inv; acc.w *= inv;

        // BIN float half: pair p = w>>1, half s = w&1
        float* Bf = (float*)BIN;
        int p = w >> 1, s = w & 1;
        Bf[((4 * lane + 0) * PADK + p) * 2 + s] = acc.x;
        Bf[((4 * lane + 1) * PADK + p) * 2 + s] = acc.y;
        Bf[((4 * lane + 2) * PADK + p) * 2 + s] = acc.z;
        Bf[((4 * lane + 3) * PADK + p) * 2 + s] = acc.w;
    }
    __syncthreads();

    // ---- layer 1: 128 -> 512; j = jg + 128*jj (jj<4), pairs pbase,pbase+1 ----
    {
        u64 acc[4][2];
        #pragma unroll
        for (int jj = 0; jj < 4; ++jj) { acc[jj][0] = 0ULL; acc[jj][1] = 0ULL; }

        const float4* Wt = (const float4*)g_wt1;    // [k*128 + jg]
        #pragma unroll 2
        for (int k = 0; k < 128; ++k) {
            float4 wv = Wt[k * 128 + jg];           // LDG.128, coalesced
            ulonglong2 ap = *(const ulonglong2*)(BIN + k * PADK + pbase);  // uniform LDS.128
            u64 w0 = pk2(wv.x, wv.x), w1 = pk2(wv.y, wv.y);
            u64 w2 = pk2(wv.z, wv.z), w3 = pk2(wv.w, wv.w);
            fma2(acc[0][0], ap.x, w0); fma2(acc[0][1], ap.y, w0);
            fma2(acc[1][0], ap.x, w1); fma2(acc[1][1], ap.y, w1);
            fma2(acc[2][0], ap.x, w2); fma2(acc[2][1], ap.y, w2);
            fma2(acc[3][0], ap.x, w3); fma2(acc[3][1], ap.y, w3);
        }
        __syncthreads();   // all BIN reads done (B2 region reused below is safe)
        #pragma unroll
        for (int jj = 0; jj < 4; ++jj) {
            int n1 = jg + 128 * jj;
            float bj = b1[n1];
            float2 v0 = upk(acc[jj][0]);
            float2 v1 = upk(acc[jj][1]);
            ulonglong2 st;
            st.x = pk2(fmaxf(v0.x + bj, 0.f), fmaxf(v0.y + bj, 0.f));
            st.y = pk2(fmaxf(v1.x + bj, 0.f), fmaxf(v1.y + bj, 0.f));
            *(ulonglong2*)(A1 + n1 * PADK + pbase) = st;     // STS.128, conflict-free (PADK)
        }
    }
    __syncthreads();

    // ---- layer 2: 512 -> 256; j = jg + 128*jj (jj<2), pairs pbase,pbase+1 ----
    {
        u64 acc[2][2];
        acc[0][0] = acc[0][1] = acc[1][0] = acc[1][1] = 0ULL;

        const float2* Wt = (const float2*)g_wt2;    // [k*128 + jg]
        #pragma unroll 4
        for (int k = 0; k < 512; ++k) {
            float2 wv = Wt[k * 128 + jg];           // LDG.64, coalesced
            ulonglong2 ap = *(const ulonglong2*)(A1 + k * PADK + pbase);   // uniform LDS.128
            u64 w0 = pk2(wv.x, wv.x), w1 = pk2(wv.y, wv.y);
            fma2(acc[0][0], ap.x, w0); fma2(acc[0][1], ap.y, w0);
            fma2(acc[1][0], ap.x, w1); fma2(acc[1][1], ap.y, w1);
        }
        #pragma unroll
        for (int jj = 0; jj < 2; ++jj) {
            int j = jg + 128 * jj;
            float bj = b2[j];
            float2 v0 = upk(acc[jj][0]);
            float2 v1 = upk(acc[jj][1]);
            ulonglong2 st;
            st.x = pk2(fmaxf(v0.x + bj, 0.f), fmaxf(v0.y + bj, 0.f));
            st.y = pk2(fmaxf(v1.x + bj, 0.f), fmaxf(v1.y + bj, 0.f));
            *(ulonglong2*)(B2 + j * PADK + pbase) = st;      // BIN dead; safe
        }
    }
    __syncthreads();

    // ---- layer 3: 256 -> 128; j = jg, pairs pbase,pbase+1 ----
    {
        u64 acc0 = 0ULL, acc1 = 0ULL;
        #pragma unroll 8
        for (int k = 0; k < 256; ++k) {
            float wv = g_wt3[k * 128 + jg];          // LDG.32, coalesced
            ulonglong2 ap = *(const ulonglong2*)(B2 + k * PADK + pbase);   // uniform LDS.128
            u64 ws = pk2(wv, wv);
            fma2(acc0, ap.x, ws); fma2(acc1, ap.y, ws);
        }
        float bj = b3[jg];
        float2 v0 = upk(acc0);
        float2 v1 = upk(acc1);
        ulonglong2 st;
        st.x = pk2(fmaxf(v0.x + bj, 0.f), fmaxf(v0.y + bj, 0.f));
        st.y = pk2(fmaxf(v1.x + bj, 0.f), fmaxf(v1.y + bj, 0.f));
        *(ulonglong2*)(A3 + jg * PADK + pbase) = st;  // A1 reads finished 2 syncs ago
    }
    __syncthreads();

    // ---- layer 4: 128 -> 2 (one warp: r = tid>>1, jo = tid&1) ----
    if (tid < 32) {
        int r  = tid >> 1;             // 0..15
        int jo = tid & 1;
        int p = r >> 1, h = r & 1;
        float acc = b4[jo];
        #pragma unroll 8
        for (int k = 0; k < 128; ++k) {
            float2 v = upk(A3[k * PADK + p]);
            acc += (h ? v.y : v.x) * W4[jo * 128 + k];
        }
        out[(r0 + r) * 2 + jo] = acc;
    }
}

// ---------------- launch ----------------
extern "C" void kernel_launch(void* const* d_in, const int* in_sizes, int n_in,
                              void* d_out, int out_size) {
    const int*   x       = (const int*)  d_in[0];
    const int*   lengths = (const int*)  d_in[1];
    const float* emb     = (const float*)d_in[2];
    const float* W1      = (const float*)d_in[3];
    const float* b1      = (const float*)d_in[4];
    const float* W2      = (const float*)d_in[5];
    const float* b2      = (const float*)d_in[6];
    const float* W3      = (const float*)d_in[7];
    const float* b3      = (const float*)d_in[8];
    const float* W4      = (const float*)d_in[9];
    const float* b4      = (const float*)d_in[10];
    float* out = (float*)d_out;

    transpose_kernel<<<(229376 + 255) / 256, 256>>>(W1, W2, W3);
    mlp_kernel<<<N_BATCH / 16, 512>>>(x, lengths, emb, b1, b2, b3, W4, b4, out);
}